// round 6
// baseline (speedup 1.0000x reference)
#include <cuda_runtime.h>
#include <cuda_bf16.h>
#include <cstdint>

// Problem constants (from reference):
//   NUM_BLOCKS=1024, BLOCK_SIZE=128, NUM_TOKENS=8192, NUM_KV_HEADS=8, HEAD_SIZE=128
// Row per (block,offset) slot = 8*128 = 1024 fp32 = 4096 B = 256 float4.

static constexpr long long INPUT_ELEMS = 8192LL * 8 * 128;  // 8,388,608
static constexpr int NUM_TOKENS = 8192;
static constexpr int NUM_ROWS = 1024 * 128;   // 131072 slot rows in the cache
static constexpr int ROW_F4 = 256;            // float4 per row
static constexpr int ROWS_PER_CTA = 4;
static constexpr int NUM_CTAS = NUM_ROWS / ROWS_PER_CTA;  // 32768
static constexpr int FILL_CTAS = NUM_TOKENS / 256;        // 32

// Inverse slot map: map[row] = token_id + 1, or 0 if no token scatters to row.
// Statically zero-initialized; consumed entries are self-cleaned each run, and
// the gate flags reset themselves, so graph replays see identical state.
__device__ int g_slot_map[NUM_ROWS];
__device__ unsigned g_fill_done = 0;
__device__ volatile int g_ready = 0;
__device__ unsigned g_consumed = 0;

// Single fused kernel:
//  phase A (CTAs 0..31): build inverse map, release gate.
//  phase B (all CTAs):   gate, then one-pass scatter-copy of 4 rows each.
//  phase C:              last CTA resets gate state for the next replay.
__global__ void __launch_bounds__(256) fused_kv_kernel(
    const float4* __restrict__ in,
    const float4* __restrict__ cache,
    const int* __restrict__ block_indices,
    const int* __restrict__ block_offset,
    float4* __restrict__ out) {
    const int lane = threadIdx.x;  // 0..255

    // ── Phase A: map fill (first 32 CTAs = exactly 8192 threads) ──
    if (blockIdx.x < FILL_CTAS) {
        const int t = blockIdx.x * 256 + lane;
        const int slot = block_indices[t] * 128 + block_offset[t];
        g_slot_map[slot] = t + 1;
        __syncthreads();
        if (lane == 0) {
            __threadfence();  // release map stores GPU-wide
            if (atomicAdd(&g_fill_done, 1) == FILL_CTAS - 1) {
                g_ready = 1;
                __threadfence();
            }
        }
    }

    // ── Gate: wait until the map is fully built ──
    if (lane == 0) {
        while (g_ready == 0) __nanosleep(64);
        __threadfence();  // acquire
    }
    __syncthreads();

    // ── Phase B: one-pass scatter-copy, 4 rows x 4 KB per CTA ──
    const int row0 = blockIdx.x * ROWS_PER_CTA;

    const float4* src[ROWS_PER_CTA];
    int tok[ROWS_PER_CTA];
    float4 v[ROWS_PER_CTA];

#pragma unroll
    for (int r = 0; r < ROWS_PER_CTA; r++) {
        const int row = row0 + r;
        tok[r] = g_slot_map[row];  // broadcast load (same addr across CTA)
        src[r] = (tok[r] != 0) ? (in + (long long)(tok[r] - 1) * ROW_F4)
                               : (cache + (long long)row * ROW_F4);
    }
#pragma unroll
    for (int r = 0; r < ROWS_PER_CTA; r++) v[r] = __ldcs(&src[r][lane]);
#pragma unroll
    for (int r = 0; r < ROWS_PER_CTA; r++)
        __stcs(&out[(long long)(row0 + r) * ROW_F4 + lane], v[r]);

    // Self-clean consumed map entries for the next replay (32 KB total).
    if (lane == 0) {
#pragma unroll
        for (int r = 0; r < ROWS_PER_CTA; r++)
            if (tok[r] != 0) g_slot_map[row0 + r] = 0;
    }

    // ── Phase C: last CTA to finish resets the gate state ──
    if (lane == 0) {
        if (atomicAdd(&g_consumed, 1) == (unsigned)(NUM_CTAS - 1)) {
            g_fill_done = 0;
            g_consumed = 0;
            __threadfence();
            g_ready = 0;
        }
    }
}

extern "C" void kernel_launch(void* const* d_in, const int* in_sizes, int n_in,
                              void* d_out, int out_size) {
    const float* input = nullptr;
    const float* cache = nullptr;
    const int* block_indices = nullptr;
    const int* block_offset = nullptr;

    // Identify inputs by element count (robust to scalar args being present or not).
    for (int i = 0; i < n_in; i++) {
        const long long sz = (long long)in_sizes[i];
        if (sz == INPUT_ELEMS && input == nullptr) {
            input = (const float*)d_in[i];
        } else if (sz == (long long)out_size && cache == nullptr) {
            cache = (const float*)d_in[i];
        } else if (sz == NUM_TOKENS) {
            if (block_indices == nullptr) block_indices = (const int*)d_in[i];
            else if (block_offset == nullptr) block_offset = (const int*)d_in[i];
        }
    }

    float* out = (float*)d_out;

    // One kernel node: fill + gate + fused scatter-copy + self-reset.
    fused_kv_kernel<<<NUM_CTAS, 256, 0, 0>>>(
        (const float4*)input, (const float4*)cache,
        block_indices, block_offset, (float4*)out);
}

// round 7
// speedup vs baseline: 1.1173x; 1.1173x over previous
#include <cuda_runtime.h>
#include <cuda_bf16.h>
#include <cstdint>

// Problem constants (from reference):
//   NUM_BLOCKS=1024, BLOCK_SIZE=128, NUM_TOKENS=8192, NUM_KV_HEADS=8, HEAD_SIZE=128
// Row per (block,offset) slot = 8*128 = 1024 fp32 = 4096 B = 256 float4.

static constexpr long long INPUT_ELEMS = 8192LL * 8 * 128;  // 8,388,608
static constexpr int NUM_TOKENS = 8192;
static constexpr int NUM_ROWS = 1024 * 128;   // 131072 slot rows in the cache
static constexpr int ROW_F4 = 256;            // float4 per row
static constexpr int ROWS_PER_CTA = 8;        // MLP=8 front-batched loads/thread

// Inverse slot map: map[row] = token_id + 1, or 0 if no token scatters to row.
// Statically zero-initialized; the main pass clears the entries it consumed,
// so every graph replay starts from an all-zero map (no memset node needed).
__device__ int g_slot_map[NUM_ROWS];

__global__ void fill_map_kernel(const int* __restrict__ block_indices,
                                const int* __restrict__ block_offset) {
    const int t = blockIdx.x * blockDim.x + threadIdx.x;
    if (t < NUM_TOKENS) {
        const int slot = block_indices[t] * 128 + block_offset[t];
        g_slot_map[slot] = t + 1;
    }
}

// One pass over the whole output. Each CTA: 8 rows x 4 KB = 32 KB.
// All 8 loads issued before any store (deep L1tex queue / high MLP).
// Streaming hints: every byte is touched exactly once.
__global__ void __launch_bounds__(256) fused_scatter_copy_kernel(
    const float4* __restrict__ in,
    const float4* __restrict__ cache,
    float4* __restrict__ out) {
    const int row0 = blockIdx.x * ROWS_PER_CTA;
    const int lane = threadIdx.x;  // 0..255

    const float4* src[ROWS_PER_CTA];
    int tok[ROWS_PER_CTA];
    float4 v[ROWS_PER_CTA];

#pragma unroll
    for (int r = 0; r < ROWS_PER_CTA; r++) {
        const int row = row0 + r;
        tok[r] = g_slot_map[row];  // broadcast load (same addr across CTA)
        src[r] = (tok[r] != 0) ? (in + (long long)(tok[r] - 1) * ROW_F4)
                               : (cache + (long long)row * ROW_F4);
    }
#pragma unroll
    for (int r = 0; r < ROWS_PER_CTA; r++) v[r] = __ldcs(&src[r][lane]);
#pragma unroll
    for (int r = 0; r < ROWS_PER_CTA; r++)
        __stcs(&out[(long long)(row0 + r) * ROW_F4 + lane], v[r]);

    // Self-clean the map for the next graph replay (32 KB total across grid).
    if (lane == 0) {
#pragma unroll
        for (int r = 0; r < ROWS_PER_CTA; r++)
            if (tok[r] != 0) g_slot_map[row0 + r] = 0;
    }
}

extern "C" void kernel_launch(void* const* d_in, const int* in_sizes, int n_in,
                              void* d_out, int out_size) {
    const float* input = nullptr;
    const float* cache = nullptr;
    const int* block_indices = nullptr;
    const int* block_offset = nullptr;

    // Identify inputs by element count (robust to scalar args being present or not).
    for (int i = 0; i < n_in; i++) {
        const long long sz = (long long)in_sizes[i];
        if (sz == INPUT_ELEMS && input == nullptr) {
            input = (const float*)d_in[i];
        } else if (sz == (long long)out_size && cache == nullptr) {
            cache = (const float*)d_in[i];
        } else if (sz == NUM_TOKENS) {
            if (block_indices == nullptr) block_indices = (const int*)d_in[i];
            else if (block_offset == nullptr) block_offset = (const int*)d_in[i];
        }
    }

    float* out = (float*)d_out;

    // 1) Build inverse map: map[slot] = token + 1 (map arrives all-zero).
    fill_map_kernel<<<(NUM_TOKENS + 255) / 256, 256, 0, 0>>>(block_indices, block_offset);

    // 2) Single fused pass producing the full output; clears the map as it goes.
    fused_scatter_copy_kernel<<<NUM_ROWS / ROWS_PER_CTA, 256, 0, 0>>>(
        (const float4*)input, (const float4*)cache, (float4*)out);
}